// round 1
// baseline (speedup 1.0000x reference)
#include <cuda_runtime.h>
#include <cuda_bf16.h>
#include <cstdint>

// Problem constants
#define B_  64
#define H_  128
#define W_  128
#define C_  3
#define KH_ 5
#define KW_ 5
#define N_  10
#define PAD_ 2

// Packed fp32x2 helpers (sm_103a FFMA2 path, PTX-only)
__device__ __forceinline__ unsigned long long pk2(float lo, float hi) {
    unsigned long long r;
    asm("mov.b64 %0, {%1, %2};" : "=l"(r) : "f"(lo), "f"(hi));
    return r;
}
__device__ __forceinline__ void unpk2(unsigned long long p, float& lo, float& hi) {
    asm("mov.b64 {%0, %1}, %2;" : "=f"(lo), "=f"(hi) : "l"(p));
}
__device__ __forceinline__ unsigned long long ffma2(unsigned long long a,
                                                    unsigned long long b,
                                                    unsigned long long c) {
    unsigned long long d;
    asm("fma.rn.f32x2 %0, %1, %2, %3;" : "=l"(d) : "l"(a), "l"(b), "l"(c));
    return d;
}

// Block: 256 threads = 128 w-columns x 2 row-pairs. Each thread computes 2
// vertically adjacent pixels (all N*C=30 outputs each), accumulating in
// fp32x2 pairs packed over n (kernel layout [B,5,5,10] has n contiguous ->
// naturally aligned 8B weight pairs in smem).
extern "C" __global__ void __launch_bounds__(256, 2)
cdna_apply_kernel(const float* __restrict__ images,
                  const float* __restrict__ kernels,
                  float* __restrict__ out) {
    const int b  = blockIdx.y;        // batch
    const int h0 = blockIdx.x * 4;    // first of 4 output rows this block owns

    __shared__ __align__(16) float s_img[8][132][3];  // rows h0-2..h0+5, cols -2..129
    __shared__ __align__(8)  float s_ker[250];        // [dh][dw][n]

    const int tid = threadIdx.x;
    const float* img = images  + (size_t)b * (H_ * W_ * C_);
    const float* ker = kernels + b * (KH_ * KW_ * N_);

    // --- cooperative loads ---
    if (tid < 250) s_ker[tid] = ker[tid];

    // s_img flat layout matches gmem row layout: row stride 396 floats
    // (132 cols * 3 c); gmem row = 384 floats, halo cols are zero.
    for (int i = tid; i < 8 * 132 * 3; i += 256) {
        const int r   = i / 396;
        const int rem = i - r * 396;
        const int gr  = h0 - 2 + r;
        float v = 0.0f;
        if ((unsigned)gr < (unsigned)H_ && rem >= 6 && rem < 390)
            v = img[gr * (W_ * C_) + rem - 6];
        (&s_img[0][0][0])[i] = v;
    }
    __syncthreads();

    const int w     = tid & 127;      // output column
    const int rp    = tid >> 7;       // which row-pair (0/1)
    const int rbase = rp * 2;         // smem row index for dh=0 of pixel0

    // acc[pixel][n_pair][c] packed fp32x2 over n (lo = n=2j, hi = n=2j+1)
    unsigned long long acc[2][5][3];
#pragma unroll
    for (int p = 0; p < 2; ++p)
#pragma unroll
        for (int j = 0; j < 5; ++j)
#pragma unroll
            for (int c = 0; c < 3; ++c) acc[p][j][c] = 0ull;

    for (int dh = 0; dh < 5; ++dh) {
        const float (*row0)[3] = s_img[rbase + dh];
        const float (*row1)[3] = s_img[rbase + dh + 1];
#pragma unroll
        for (int dw = 0; dw < 5; ++dw) {
            // broadcast image values, duplicated into both fp32x2 lanes
            unsigned long long i0[3], i1[3];
#pragma unroll
            for (int c = 0; c < 3; ++c) {
                const float v0 = row0[w + dw][c];
                const float v1 = row1[w + dw][c];
                i0[c] = pk2(v0, v0);
                i1[c] = pk2(v1, v1);
            }
            // weight n-pairs: contiguous + 8B aligned -> LDS.64
            const unsigned long long* kp =
                reinterpret_cast<const unsigned long long*>(&s_ker[(dh * 5 + dw) * 10]);
#pragma unroll
            for (int j = 0; j < 5; ++j) {
                const unsigned long long kw2 = kp[j];
#pragma unroll
                for (int c = 0; c < 3; ++c) {
                    acc[0][j][c] = ffma2(i0[c], kw2, acc[0][j][c]);
                    acc[1][j][c] = ffma2(i1[c], kw2, acc[1][j][c]);
                }
            }
        }
    }

    // --- store: out[n][b][c][h][w], w contiguous across warp -> coalesced ---
    const int hpix = h0 + rp * 2;     // pixel0 global row; pixel1 = +1
#pragma unroll
    for (int j = 0; j < 5; ++j) {
#pragma unroll
        for (int c = 0; c < 3; ++c) {
            float lo0, hi0, lo1, hi1;
            unpk2(acc[0][j][c], lo0, hi0);
            unpk2(acc[1][j][c], lo1, hi1);
            const int base_lo = (((2 * j)     * B_ + b) * C_ + c) * (H_ * W_);
            const int base_hi = (((2 * j + 1) * B_ + b) * C_ + c) * (H_ * W_);
            out[base_lo + hpix * W_ + w]       = lo0;
            out[base_hi + hpix * W_ + w]       = hi0;
            out[base_lo + (hpix + 1) * W_ + w] = lo1;
            out[base_hi + (hpix + 1) * W_ + w] = hi1;
        }
    }
}

extern "C" void kernel_launch(void* const* d_in, const int* in_sizes, int n_in,
                              void* d_out, int out_size) {
    const float* images  = (const float*)d_in[0];  // [64,128,128,3]
    const float* kernels = (const float*)d_in[1];  // [64,5,5,10]
    float* out = (float*)d_out;                    // [10,64,3,128,128]
    (void)in_sizes; (void)n_in; (void)out_size;

    dim3 grid(H_ / 4, B_);   // 32 x 64 blocks
    dim3 block(256);
    cdna_apply_kernel<<<grid, block>>>(images, kernels, out);
}

// round 2
// speedup vs baseline: 1.0538x; 1.0538x over previous
#include <cuda_runtime.h>
#include <cuda_bf16.h>
#include <cstdint>

// Problem constants
#define B_  64
#define H_  128
#define W_  128
#define C_  3
#define KH_ 5
#define KW_ 5
#define N_  10
#define PAD_ 2

// Packed fp32x2 helpers (sm_103a FFMA2 path, PTX-only)
__device__ __forceinline__ unsigned long long pk2(float lo, float hi) {
    unsigned long long r;
    asm("mov.b64 %0, {%1, %2};" : "=l"(r) : "f"(lo), "f"(hi));
    return r;
}
__device__ __forceinline__ void unpk2(unsigned long long p, float& lo, float& hi) {
    asm("mov.b64 {%0, %1}, %2;" : "=f"(lo), "=f"(hi) : "l"(p));
}
__device__ __forceinline__ unsigned long long ffma2(unsigned long long a,
                                                    unsigned long long b,
                                                    unsigned long long c) {
    unsigned long long d;
    asm("fma.rn.f32x2 %0, %1, %2, %3;" : "=l"(d) : "l"(a), "l"(b), "l"(c));
    return d;
}

// Block: 256 threads = 128 w-columns x 2 rows. Each thread computes ONE pixel,
// all N*C = 30 outputs, accumulated as 15 fp32x2 pairs packed over n
// (kernel layout [B,5,5,10]: n contiguous -> aligned 8B weight pairs in smem).
// 1 pixel/thread keeps accs at 30 regs -> 3 CTAs/SM (24 warps) instead of 2.
extern "C" __global__ void __launch_bounds__(256, 3)
cdna_apply_kernel(const float* __restrict__ images,
                  const float* __restrict__ kernels,
                  float* __restrict__ out) {
    const int b  = blockIdx.y;        // batch
    const int h0 = blockIdx.x * 2;    // first of 2 output rows this block owns

    __shared__ __align__(16) float s_img[6][132][3];  // rows h0-2..h0+3, cols -2..129
    __shared__ __align__(8)  float s_ker[250];        // [dh][dw][n]

    const int tid = threadIdx.x;
    const float* img = images  + (size_t)b * (H_ * W_ * C_);
    const float* ker = kernels + b * (KH_ * KW_ * N_);

    // --- cooperative loads ---
    if (tid < 250) s_ker[tid] = ker[tid];

    // s_img flat layout matches gmem row layout: row stride 396 floats
    // (132 cols * 3 c); gmem row = 384 floats, halo cols are zero.
    for (int i = tid; i < 6 * 132 * 3; i += 256) {
        const int r   = i / 396;
        const int rem = i - r * 396;
        const int gr  = h0 - 2 + r;
        float v = 0.0f;
        if ((unsigned)gr < (unsigned)H_ && rem >= 6 && rem < 390)
            v = img[gr * (W_ * C_) + rem - 6];
        (&s_img[0][0][0])[i] = v;
    }
    __syncthreads();

    const int w  = tid & 127;   // output column
    const int hr = tid >> 7;    // row within block (0/1); smem dh=0 row = hr

    // acc[n_pair][c] packed fp32x2 over n (lo = n=2j, hi = n=2j+1)
    unsigned long long acc[5][3];
#pragma unroll
    for (int j = 0; j < 5; ++j)
#pragma unroll
        for (int c = 0; c < 3; ++c) acc[j][c] = 0ull;

#pragma unroll
    for (int dh = 0; dh < 5; ++dh) {
        const float (*row)[3] = s_img[hr + dh];
#pragma unroll
        for (int dw = 0; dw < 5; ++dw) {
            // broadcast image values, duplicated into both fp32x2 lanes
            unsigned long long iv[3];
#pragma unroll
            for (int c = 0; c < 3; ++c) {
                const float v = row[w + dw][c];
                iv[c] = pk2(v, v);
            }
            // weight n-pairs: contiguous + 8B aligned -> LDS.64 broadcast
            const unsigned long long* kp =
                reinterpret_cast<const unsigned long long*>(&s_ker[(dh * 5 + dw) * 10]);
#pragma unroll
            for (int j = 0; j < 5; ++j) {
                const unsigned long long kw2 = kp[j];
#pragma unroll
                for (int c = 0; c < 3; ++c)
                    acc[j][c] = ffma2(iv[c], kw2, acc[j][c]);
            }
        }
    }

    // --- store: out[n][b][c][h][w], w contiguous across warp -> coalesced ---
    const int hpix = h0 + hr;
#pragma unroll
    for (int j = 0; j < 5; ++j) {
#pragma unroll
        for (int c = 0; c < 3; ++c) {
            float lo, hi;
            unpk2(acc[j][c], lo, hi);
            const int base_lo = (((2 * j)     * B_ + b) * C_ + c) * (H_ * W_);
            const int base_hi = (((2 * j + 1) * B_ + b) * C_ + c) * (H_ * W_);
            out[base_lo + hpix * W_ + w] = lo;
            out[base_hi + hpix * W_ + w] = hi;
        }
    }
}

extern "C" void kernel_launch(void* const* d_in, const int* in_sizes, int n_in,
                              void* d_out, int out_size) {
    const float* images  = (const float*)d_in[0];  // [64,128,128,3]
    const float* kernels = (const float*)d_in[1];  // [64,5,5,10]
    float* out = (float*)d_out;                    // [10,64,3,128,128]
    (void)in_sizes; (void)n_in; (void)out_size;

    dim3 grid(H_ / 2, B_);   // 64 x 64 blocks
    dim3 block(256);
    cdna_apply_kernel<<<grid, block>>>(images, kernels, out);
}

// round 3
// speedup vs baseline: 1.2440x; 1.1805x over previous
#include <cuda_runtime.h>
#include <cuda_bf16.h>
#include <cstdint>

// Problem constants
#define B_  64
#define H_  128
#define W_  128
#define C_  3
#define KH_ 5
#define KW_ 5
#define N_  10
#define PAD_ 2

// Packed fp32x2 helpers (sm_103a FFMA2 path, PTX-only)
__device__ __forceinline__ unsigned long long pk2(float lo, float hi) {
    unsigned long long r;
    asm("mov.b64 %0, {%1, %2};" : "=l"(r) : "f"(lo), "f"(hi));
    return r;
}
__device__ __forceinline__ void unpk2(unsigned long long p, float& lo, float& hi) {
    asm("mov.b64 {%0, %1}, %2;" : "=f"(lo), "=f"(hi) : "l"(p));
}
__device__ __forceinline__ unsigned long long ffma2(unsigned long long a,
                                                    unsigned long long b,
                                                    unsigned long long c) {
    unsigned long long d;
    asm("fma.rn.f32x2 %0, %1, %2, %3;" : "=l"(d) : "l"(a), "l"(b), "l"(c));
    return d;
}

// Block: 256 threads = 128 w-columns x 2 rows; one pixel per thread, all
// N*C=30 outputs as 15 fp32x2 accs packed over n. Weight smem padded to
// 12 floats/tap so the 5 n-pairs load as 2x LDS.128 + 1x LDS.64.
// dh loop rolled to keep live regs <= 64 -> 4 CTAs/SM.
extern "C" __global__ void __launch_bounds__(256, 4)
cdna_apply_kernel(const float* __restrict__ images,
                  const float* __restrict__ kernels,
                  float* __restrict__ out) {
    const int b  = blockIdx.y;        // batch
    const int h0 = blockIdx.x * 2;    // first of 2 output rows this block owns

    __shared__ __align__(16) float s_img[6][132][3];  // rows h0-2..h0+3, cols -2..129
    __shared__ __align__(16) float s_ker[25][12];     // [tap][n padded 10->12]

    const int tid = threadIdx.x;
    const float* img = images  + (size_t)b * (H_ * W_ * C_);
    const float* ker = kernels + b * (KH_ * KW_ * N_);

    // --- cooperative loads ---
    if (tid < 250) {
        const int tap = tid / 10;
        const int n   = tid - tap * 10;
        s_ker[tap][n] = ker[tid];
    }

    // s_img flat layout matches gmem row layout: row stride 396 floats
    // (132 cols * 3 c); gmem row = 384 floats, halo cols are zero.
    for (int i = tid; i < 6 * 132 * 3; i += 256) {
        const int r   = i / 396;
        const int rem = i - r * 396;
        const int gr  = h0 - 2 + r;
        float v = 0.0f;
        if ((unsigned)gr < (unsigned)H_ && rem >= 6 && rem < 390)
            v = img[gr * (W_ * C_) + rem - 6];
        (&s_img[0][0][0])[i] = v;
    }
    __syncthreads();

    const int w  = tid & 127;   // output column
    const int hr = tid >> 7;    // row within block (0/1); smem dh=0 row = hr

    // acc[n_pair][c] packed fp32x2 over n (lo = n=2j, hi = n=2j+1)
    unsigned long long acc[5][3];
#pragma unroll
    for (int j = 0; j < 5; ++j)
#pragma unroll
        for (int c = 0; c < 3; ++c) acc[j][c] = 0ull;

    // Rolled dh loop (5 iters) keeps live register set small; inner dw x n x c
    // fully unrolled: per tap 3 img LDS + 3 dup movs + 3 vec wt LDS + 15 FFMA2.
    for (int dh = 0; dh < 5; ++dh) {
        const float* row = &s_img[hr + dh][w][0];
        const float* kt  = &s_ker[dh * 5][0];
#pragma unroll
        for (int dw = 0; dw < 5; ++dw) {
            // image values, duplicated into both fp32x2 lanes
            unsigned long long iv[3];
#pragma unroll
            for (int c = 0; c < 3; ++c) {
                const float v = row[dw * 3 + c];
                iv[c] = pk2(v, v);
            }
            // weight n-pairs: 48B-aligned tap row -> LDS.128 + LDS.128 + LDS.64
            const float* kp = kt + dw * 12;
            uint4 w01 = *reinterpret_cast<const uint4*>(kp);      // pairs j=0,1
            uint4 w23 = *reinterpret_cast<const uint4*>(kp + 4);  // pairs j=2,3
            unsigned long long w4 = *reinterpret_cast<const unsigned long long*>(kp + 8);
            unsigned long long kw2[5];
            kw2[0] = (unsigned long long)w01.x | ((unsigned long long)w01.y << 32);
            kw2[1] = (unsigned long long)w01.z | ((unsigned long long)w01.w << 32);
            kw2[2] = (unsigned long long)w23.x | ((unsigned long long)w23.y << 32);
            kw2[3] = (unsigned long long)w23.z | ((unsigned long long)w23.w << 32);
            kw2[4] = w4;
#pragma unroll
            for (int j = 0; j < 5; ++j)
#pragma unroll
                for (int c = 0; c < 3; ++c)
                    acc[j][c] = ffma2(iv[c], kw2[j], acc[j][c]);
        }
    }

    // --- store: out[n][b][c][h][w], w contiguous across warp -> coalesced ---
    const int hpix = h0 + hr;
#pragma unroll
    for (int j = 0; j < 5; ++j) {
#pragma unroll
        for (int c = 0; c < 3; ++c) {
            float lo, hi;
            unpk2(acc[j][c], lo, hi);
            const int base_lo = (((2 * j)     * B_ + b) * C_ + c) * (H_ * W_);
            const int base_hi = (((2 * j + 1) * B_ + b) * C_ + c) * (H_ * W_);
            out[base_lo + hpix * W_ + w] = lo;
            out[base_hi + hpix * W_ + w] = hi;
        }
    }
}

extern "C" void kernel_launch(void* const* d_in, const int* in_sizes, int n_in,
                              void* d_out, int out_size) {
    const float* images  = (const float*)d_in[0];  // [64,128,128,3]
    const float* kernels = (const float*)d_in[1];  // [64,5,5,10]
    float* out = (float*)d_out;                    // [10,64,3,128,128]
    (void)in_sizes; (void)n_in; (void)out_size;

    dim3 grid(H_ / 2, B_);   // 64 x 64 blocks
    dim3 block(256);
    cdna_apply_kernel<<<grid, block>>>(images, kernels, out);
}

// round 4
// speedup vs baseline: 1.3475x; 1.0831x over previous
#include <cuda_runtime.h>
#include <cuda_bf16.h>
#include <cstdint>

// Problem constants
#define B_  64
#define H_  128
#define W_  128
#define C_  3
#define KH_ 5
#define KW_ 5
#define N_  10
#define PAD_ 2
#define HW_ (H_ * W_)

// Packed fp32x2 helpers (sm_103a FFMA2 path, PTX-only)
__device__ __forceinline__ unsigned long long pk2(float lo, float hi) {
    unsigned long long r;
    asm("mov.b64 %0, {%1, %2};" : "=l"(r) : "f"(lo), "f"(hi));
    return r;
}
__device__ __forceinline__ void unpk2(unsigned long long p, float& lo, float& hi) {
    asm("mov.b64 {%0, %1}, %2;" : "=f"(lo), "=f"(hi) : "l"(p));
}
__device__ __forceinline__ unsigned long long ffma2(unsigned long long a,
                                                    unsigned long long b,
                                                    unsigned long long c) {
    unsigned long long d;
    asm("fma.rn.f32x2 %0, %1, %2, %3;" : "=l"(d) : "l"(a), "l"(b), "l"(c));
    return d;
}

// Block: 256 threads = 128 w-columns x 2 rows; one pixel per thread, all
// N*C=30 outputs as 15 fp32x2 accs packed over n. Weight smem padded to
// 12 floats/tap; loads are ulonglong2 (LDS.128 -> two u64 pairs, zero
// repacking ALU) + one u64 (LDS.64). All 25 taps fully unrolled.
extern "C" __global__ void __launch_bounds__(256, 4)
cdna_apply_kernel(const float* __restrict__ images,
                  const float* __restrict__ kernels,
                  float* __restrict__ out) {
    const int b  = blockIdx.y;        // batch
    const int h0 = blockIdx.x * 2;    // first of 2 output rows this block owns

    __shared__ __align__(16) float s_img[6][132][3];  // rows h0-2..h0+3, cols -2..129
    __shared__ __align__(16) float s_ker[25][12];     // [tap][n padded 10->12]

    const int tid = threadIdx.x;
    const float* img = images  + (size_t)b * (H_ * W_ * C_);
    const float* ker = kernels + b * (KH_ * KW_ * N_);

    // --- cooperative loads ---
    if (tid < 250) {
        const int tap = tid / 10;
        const int n   = tid - tap * 10;
        s_ker[tap][n] = ker[tid];
    }

    // s_img flat layout matches gmem row layout: row stride 396 floats
    // (132 cols * 3 c); gmem row = 384 floats, halo cols are zero.
    for (int i = tid; i < 6 * 132 * 3; i += 256) {
        const int r   = i / 396;
        const int rem = i - r * 396;
        const int gr  = h0 - 2 + r;
        float v = 0.0f;
        if ((unsigned)gr < (unsigned)H_ && rem >= 6 && rem < 390)
            v = img[gr * (W_ * C_) + rem - 6];
        (&s_img[0][0][0])[i] = v;
    }
    __syncthreads();

    const int w  = tid & 127;   // output column
    const int hr = tid >> 7;    // row within block (0/1); smem dh=0 row = hr

    // acc[n_pair][c] packed fp32x2 over n (lo = n=2j, hi = n=2j+1)
    unsigned long long acc[5][3];
#pragma unroll
    for (int j = 0; j < 5; ++j)
#pragma unroll
        for (int c = 0; c < 3; ++c) acc[j][c] = 0ull;

    const float* rowbase = &s_img[hr][w][0];   // dh advances by 396 floats

#pragma unroll
    for (int dh = 0; dh < 5; ++dh) {
        const float* row = rowbase + dh * (132 * 3);
#pragma unroll
        for (int dw = 0; dw < 5; ++dw) {
            // image values, duplicated into both fp32x2 lanes
            unsigned long long iv0 = 0, iv1 = 0, iv2 = 0;
            {
                const float v0 = row[dw * 3 + 0];
                const float v1 = row[dw * 3 + 1];
                const float v2 = row[dw * 3 + 2];
                iv0 = pk2(v0, v0);
                iv1 = pk2(v1, v1);
                iv2 = pk2(v2, v2);
            }
            // weight n-pairs: 48B-aligned tap row -> LDS.128 + LDS.128 + LDS.64
            const float* kp = &s_ker[dh * 5 + dw][0];
            const ulonglong2 wA = *reinterpret_cast<const ulonglong2*>(kp);      // pairs 0,1
            const ulonglong2 wB = *reinterpret_cast<const ulonglong2*>(kp + 4);  // pairs 2,3
            const unsigned long long w4 =
                *reinterpret_cast<const unsigned long long*>(kp + 8);            // pair 4

            acc[0][0] = ffma2(iv0, wA.x, acc[0][0]);
            acc[0][1] = ffma2(iv1, wA.x, acc[0][1]);
            acc[0][2] = ffma2(iv2, wA.x, acc[0][2]);
            acc[1][0] = ffma2(iv0, wA.y, acc[1][0]);
            acc[1][1] = ffma2(iv1, wA.y, acc[1][1]);
            acc[1][2] = ffma2(iv2, wA.y, acc[1][2]);
            acc[2][0] = ffma2(iv0, wB.x, acc[2][0]);
            acc[2][1] = ffma2(iv1, wB.x, acc[2][1]);
            acc[2][2] = ffma2(iv2, wB.x, acc[2][2]);
            acc[3][0] = ffma2(iv0, wB.y, acc[3][0]);
            acc[3][1] = ffma2(iv1, wB.y, acc[3][1]);
            acc[3][2] = ffma2(iv2, wB.y, acc[3][2]);
            acc[4][0] = ffma2(iv0, w4, acc[4][0]);
            acc[4][1] = ffma2(iv1, w4, acc[4][1]);
            acc[4][2] = ffma2(iv2, w4, acc[4][2]);
        }
    }

    // --- store: out[n][b][c][h][w], w contiguous across warp -> coalesced ---
    // Strength-reduced addressing: one base, per-n bases by constant adds,
    // per-c constant immediate offsets.
    const int hpix = h0 + hr;
    float* o = out + (size_t)b * (C_ * HW_) + hpix * W_ + w;  // n=0, c=0
#pragma unroll
    for (int j = 0; j < 5; ++j) {
        float* o_lo = o + (size_t)(2 * j)     * (B_ * C_ * HW_);
        float* o_hi = o + (size_t)(2 * j + 1) * (B_ * C_ * HW_);
#pragma unroll
        for (int c = 0; c < 3; ++c) {
            float lo, hi;
            unpk2(acc[j][c], lo, hi);
            o_lo[c * HW_] = lo;
            o_hi[c * HW_] = hi;
        }
    }
}

extern "C" void kernel_launch(void* const* d_in, const int* in_sizes, int n_in,
                              void* d_out, int out_size) {
    const float* images  = (const float*)d_in[0];  // [64,128,128,3]
    const float* kernels = (const float*)d_in[1];  // [64,5,5,10]
    float* out = (float*)d_out;                    // [10,64,3,128,128]
    (void)in_sizes; (void)n_in; (void)out_size;

    dim3 grid(H_ / 2, B_);   // 64 x 64 blocks
    dim3 block(256);
    cdna_apply_kernel<<<grid, block>>>(images, kernels, out);
}